// round 1
// baseline (speedup 1.0000x reference)
#include <cuda_runtime.h>
#include <cuda_bf16.h>
#include <math.h>

// ---------------------------------------------------------------------------
// Problem constants
// ---------------------------------------------------------------------------
#define B_   1024
#define D_   1024
#define H4   4096
#define BAR_ 32
#define EPS_ 1e-5f

// ---------------------------------------------------------------------------
// Scratch (device globals: no allocations allowed)
// ---------------------------------------------------------------------------
__device__ float g_zn   [B_ * D_];
__device__ float g_h0   [B_ * D_];
__device__ float g_c0   [B_ * D_];
__device__ float g_h1   [B_ * D_];
__device__ float g_c1   [B_ * D_];
__device__ float g_x0p  [B_ * H4];          // x0_proj (+ both layer-0 biases)
__device__ float g_gates[B_ * H4];
__device__ float g_feats[(size_t)B_ * BAR_ * D_];   // (B, 32, H)
__device__ float g_scale[D_];
__device__ float g_shift[D_];
__device__ float g_b0   [H4];               // b_ih0 + b_hh0
__device__ float g_b1   [H4];               // b_ih1 + b_hh1

// ---------------------------------------------------------------------------
// BatchNorm statistics: one block handles 32 columns, blockDim = (32, 8)
// ---------------------------------------------------------------------------
__global__ void bn_stats_kernel(const float* __restrict__ z,
                                const float* __restrict__ gamma,
                                const float* __restrict__ beta) {
    __shared__ float ssum[8][32];
    __shared__ float ssq [8][32];
    int col = blockIdx.x * 32 + threadIdx.x;
    float s = 0.f, q = 0.f;
    for (int r = threadIdx.y; r < B_; r += 8) {
        float v = z[(size_t)r * D_ + col];
        s += v;
        q += v * v;
    }
    ssum[threadIdx.y][threadIdx.x] = s;
    ssq [threadIdx.y][threadIdx.x] = q;
    __syncthreads();
    if (threadIdx.y == 0) {
#pragma unroll
        for (int y = 1; y < 8; y++) {
            s += ssum[y][threadIdx.x];
            q += ssq [y][threadIdx.x];
        }
        float mean = s * (1.f / (float)B_);
        float var  = q * (1.f / (float)B_) - mean * mean;
        float sc   = gamma[col] * rsqrtf(var + EPS_);
        g_scale[col] = sc;
        g_shift[col] = beta[col] - mean * sc;
    }
}

// Apply BN and initialize zn, h0, c0, h1, c1 (all equal zn)
__global__ void bn_apply_init_kernel(const float* __restrict__ z) {
    int idx = blockIdx.x * blockDim.x + threadIdx.x;
    int col = idx & (D_ - 1);
    float v = z[idx] * g_scale[col] + g_shift[col];
    g_zn[idx] = v;
    g_h0[idx] = v; g_c0[idx] = v;
    g_h1[idx] = v; g_c1[idx] = v;
}

// Precompute combined biases
__global__ void bias_sum_kernel(const float* __restrict__ b_ih0,
                                const float* __restrict__ b_hh0,
                                const float* __restrict__ b_ih1,
                                const float* __restrict__ b_hh1) {
    int i = blockIdx.x * blockDim.x + threadIdx.x;
    if (i < H4) {
        g_b0[i] = b_ih0[i] + b_hh0[i];
        g_b1[i] = b_ih1[i] + b_hh1[i];
    }
}

// ---------------------------------------------------------------------------
// Generic fp32 GEMM:  C[M,N] = (Cinit? Cinit : 0) + (bias? bias : 0)
//                              + A1[M,K1] @ B1[N,K1]^T  (+ A2[M,K2] @ B2[N,K2]^T)
// Both A and B are K-major (row stride == their K). Tile 128x128x16,
// 256 threads, 8x8 per thread. All dims assumed multiples of the tile.
// ---------------------------------------------------------------------------
#define BM 128
#define BN 128
#define BK 16
#define TM 8
#define TN 8

__global__ __launch_bounds__(256, 2)
void gemm_kernel(const float* __restrict__ A1, const float* __restrict__ B1, int K1,
                 const float* __restrict__ A2, const float* __restrict__ B2, int K2,
                 const float* __restrict__ Cinit, const float* __restrict__ bias,
                 float* __restrict__ C, int M, int N) {
    __shared__ float As[BK][BM + 4];
    __shared__ float Bs[BK][BN + 4];

    const int tid = threadIdx.x;
    const int tx = tid & 15;       // 0..15 -> N direction
    const int ty = tid >> 4;       // 0..15 -> M direction
    const int row0 = blockIdx.y * BM;
    const int col0 = blockIdx.x * BN;

    const int lr = tid >> 2;       // 0..63 loader row
    const int lc = tid & 3;        // 0..3  loader float4 column

    float acc[TM][TN];
#pragma unroll
    for (int i = 0; i < TM; i++)
#pragma unroll
        for (int j = 0; j < TN; j++) acc[i][j] = 0.f;

    const int Ktot = K1 + K2;
    for (int k0 = 0; k0 < Ktot; k0 += BK) {
        const float* A; const float* Bm; int kk, ldk;
        if (k0 < K1) { A = A1; Bm = B1; kk = k0;      ldk = K1; }
        else         { A = A2; Bm = B2; kk = k0 - K1; ldk = K2; }

#pragma unroll
        for (int s = 0; s < 2; s++) {
            int r = lr + s * 64;
            float4 va = *(const float4*)(A  + (size_t)(row0 + r) * ldk + kk + lc * 4);
            As[lc * 4 + 0][r] = va.x;
            As[lc * 4 + 1][r] = va.y;
            As[lc * 4 + 2][r] = va.z;
            As[lc * 4 + 3][r] = va.w;
            float4 vb = *(const float4*)(Bm + (size_t)(col0 + r) * ldk + kk + lc * 4);
            Bs[lc * 4 + 0][r] = vb.x;
            Bs[lc * 4 + 1][r] = vb.y;
            Bs[lc * 4 + 2][r] = vb.z;
            Bs[lc * 4 + 3][r] = vb.w;
        }
        __syncthreads();

#pragma unroll
        for (int k = 0; k < BK; k++) {
            float a[TM], b[TN];
            float4 a0 = *(const float4*)&As[k][ty * TM];
            float4 a1 = *(const float4*)&As[k][ty * TM + 4];
            a[0]=a0.x; a[1]=a0.y; a[2]=a0.z; a[3]=a0.w;
            a[4]=a1.x; a[5]=a1.y; a[6]=a1.z; a[7]=a1.w;
            float4 b0 = *(const float4*)&Bs[k][tx * TN];
            float4 b1 = *(const float4*)&Bs[k][tx * TN + 4];
            b[0]=b0.x; b[1]=b0.y; b[2]=b0.z; b[3]=b0.w;
            b[4]=b1.x; b[5]=b1.y; b[6]=b1.z; b[7]=b1.w;
#pragma unroll
            for (int i = 0; i < TM; i++)
#pragma unroll
                for (int j = 0; j < TN; j++)
                    acc[i][j] = fmaf(a[i], b[j], acc[i][j]);
        }
        __syncthreads();
    }

    // Epilogue
#pragma unroll
    for (int i = 0; i < TM; i++) {
        int m = row0 + ty * TM + i;
        size_t base = (size_t)m * N + col0 + tx * TN;
#pragma unroll
        for (int jj = 0; jj < TN; jj += 4) {
            float4 v;
            v.x = acc[i][jj + 0];
            v.y = acc[i][jj + 1];
            v.z = acc[i][jj + 2];
            v.w = acc[i][jj + 3];
            int n = col0 + tx * TN + jj;
            if (bias) {
                v.x += bias[n + 0]; v.y += bias[n + 1];
                v.z += bias[n + 2]; v.w += bias[n + 3];
            }
            if (Cinit) {
                float4 ci = *(const float4*)(Cinit + base + jj);
                v.x += ci.x; v.y += ci.y; v.z += ci.z; v.w += ci.w;
            }
            *(float4*)(C + base + jj) = v;
        }
    }
}

// ---------------------------------------------------------------------------
// LSTM cell elementwise: gates (B,4H) order (i,f,g,o); in-place h,c update.
// Optionally scatter h_new into feats at step t.
// ---------------------------------------------------------------------------
__device__ __forceinline__ float sigmoidf_(float x) {
    return 1.f / (1.f + expf(-x));
}

__global__ void lstm_cell_kernel(const float* __restrict__ gates,
                                 float* __restrict__ h, float* __restrict__ c,
                                 float* __restrict__ feats, int t) {
    int idx = blockIdx.x * blockDim.x + threadIdx.x;   // 0 .. B*H-1
    int b  = idx >> 10;
    int hh = idx & (D_ - 1);
    const float* gr = gates + (size_t)b * H4;
    float gi = sigmoidf_(gr[hh]);
    float gf = sigmoidf_(gr[D_ + hh]);
    float gg = tanhf    (gr[2 * D_ + hh]);
    float go = sigmoidf_(gr[3 * D_ + hh]);
    float cn = gf * c[idx] + gi * gg;
    float hn = go * tanhf(cn);
    c[idx] = cn;
    h[idx] = hn;
    if (feats) feats[((size_t)b * BAR_ + t) * D_ + hh] = hn;
}

// ---------------------------------------------------------------------------
// Launch
// ---------------------------------------------------------------------------
extern "C" void kernel_launch(void* const* d_in, const int* in_sizes, int n_in,
                              void* d_out, int out_size) {
    const float* z       = (const float*)d_in[0];
    const float* gamma   = (const float*)d_in[1];
    const float* beta    = (const float*)d_in[2];
    const float* W_ih0   = (const float*)d_in[3];
    const float* W_hh0   = (const float*)d_in[4];
    const float* b_ih0   = (const float*)d_in[5];
    const float* b_hh0   = (const float*)d_in[6];
    const float* W_ih1   = (const float*)d_in[7];
    const float* W_hh1   = (const float*)d_in[8];
    const float* b_ih1   = (const float*)d_in[9];
    const float* b_hh1   = (const float*)d_in[10];
    const float* W_lin   = (const float*)d_in[11];
    const float* b_lin   = (const float*)d_in[12];
    float* out = (float*)d_out;

    float *zn, *h0, *c0, *h1, *c1, *x0p, *gates, *feats, *b0, *b1;
    cudaGetSymbolAddress((void**)&zn,    g_zn);
    cudaGetSymbolAddress((void**)&h0,    g_h0);
    cudaGetSymbolAddress((void**)&c0,    g_c0);
    cudaGetSymbolAddress((void**)&h1,    g_h1);
    cudaGetSymbolAddress((void**)&c1,    g_c1);
    cudaGetSymbolAddress((void**)&x0p,   g_x0p);
    cudaGetSymbolAddress((void**)&gates, g_gates);
    cudaGetSymbolAddress((void**)&feats, g_feats);
    cudaGetSymbolAddress((void**)&b0,    g_b0);
    cudaGetSymbolAddress((void**)&b1,    g_b1);

    // 1. BatchNorm + state init
    bn_stats_kernel<<<D_ / 32, dim3(32, 8)>>>(z, gamma, beta);
    bn_apply_init_kernel<<<(B_ * D_) / 512, 512>>>(z);
    bias_sum_kernel<<<H4 / 256, 256>>>(b_ih0, b_hh0, b_ih1, b_hh1);

    // 2. x0_proj = zn @ W_ih0^T + (b_ih0 + b_hh0)
    gemm_kernel<<<dim3(H4 / BN, B_ / BM), 256>>>(
        zn, W_ih0, D_, nullptr, nullptr, 0, nullptr, b0, x0p, B_, H4);

    // 3. 32 recurrent steps
    for (int t = 0; t < BAR_; t++) {
        // layer 0: gates = x0_proj + h0 @ W_hh0^T
        gemm_kernel<<<dim3(H4 / BN, B_ / BM), 256>>>(
            h0, W_hh0, D_, nullptr, nullptr, 0, x0p, nullptr, gates, B_, H4);
        lstm_cell_kernel<<<(B_ * D_) / 512, 512>>>(gates, h0, c0, nullptr, 0);

        // layer 1: gates = h0 @ W_ih1^T + h1 @ W_hh1^T + (b_ih1 + b_hh1)
        gemm_kernel<<<dim3(H4 / BN, B_ / BM), 256>>>(
            h0, W_ih1, D_, h1, W_hh1, D_, nullptr, b1, gates, B_, H4);
        lstm_cell_kernel<<<(B_ * D_) / 512, 512>>>(gates, h1, c1, feats, t);
    }

    // 4. out = feats(B*32, H) @ W_lin^T + b_lin
    gemm_kernel<<<dim3(D_ / BN, (B_ * BAR_) / BM), 256>>>(
        feats, W_lin, D_, nullptr, nullptr, 0, nullptr, b_lin, out,
        B_ * BAR_, D_);
}